// round 1
// baseline (speedup 1.0000x reference)
#include <cuda_runtime.h>

#define M_TOTAL 12608   // 64 * 197
#define K_DIM   768
#define R_DIM   192
#define BM      128
#define BN      64
#define BK      16

__device__ __forceinline__ float gelu_exact(float x) {
    // 0.5 * x * (1 + erf(x / sqrt(2)))
    return 0.5f * x * (1.0f + erff(x * 0.70710678118654752f));
}

__global__ __launch_bounds__(256, 2)
void qkv_gelu_kernel(const float* __restrict__ X,
                     const float* __restrict__ Wq,
                     const float* __restrict__ Wk,
                     const float* __restrict__ Wv,
                     float* __restrict__ Out)
{
    __shared__ float As[BK][BM];   // A tile transposed: As[k][m]
    __shared__ float Bs[BK][BN];   // B tile: Bs[k][n]

    const int tid = threadIdx.x;          // 0..255
    const int bm  = blockIdx.y * BM;      // m-tile origin
    const int nb  = blockIdx.x;           // 0..8 (n-tile index, 9 * 64 = 576)

    // Each 64-wide n-tile lies entirely inside one weight matrix (64 | 192).
    const int wsel   = nb / 3;
    const int colofs = (nb % 3) * BN;
    const float* __restrict__ W = (wsel == 0) ? Wq : (wsel == 1) ? Wk : Wv;
    float* __restrict__ outbase = Out + (size_t)wsel * (size_t)M_TOTAL * R_DIM + colofs;

    const int tr = tid >> 4;   // 0..15 -> rows  [tr*8, tr*8+8)
    const int tc = tid & 15;   // 0..15 -> cols  [tc*4, tc*4+4)

    float acc[8][4];
    #pragma unroll
    for (int i = 0; i < 8; ++i)
        #pragma unroll
        for (int j = 0; j < 4; ++j)
            acc[i][j] = 0.0f;

    // B-load mapping: one float4 per thread (16 rows x 64 cols = 256 float4)
    const int brow = tid >> 4;          // 0..15
    const int bcol = (tid & 15) * 4;    // 0..60

    for (int k0 = 0; k0 < K_DIM; k0 += BK) {
        // ---- Load A tile: 128 rows x 16 k, two float4 per thread, store transposed
        #pragma unroll
        for (int l = 0; l < 2; ++l) {
            int id   = tid + l * 256;        // 0..511
            int arow = id >> 2;              // 0..127
            int acol = (id & 3) * 4;         // 0,4,8,12
            int grow = bm + arow;
            float4 v = make_float4(0.f, 0.f, 0.f, 0.f);
            if (grow < M_TOTAL)
                v = *reinterpret_cast<const float4*>(&X[(size_t)grow * K_DIM + k0 + acol]);
            As[acol + 0][arow] = v.x;
            As[acol + 1][arow] = v.y;
            As[acol + 2][arow] = v.z;
            As[acol + 3][arow] = v.w;
        }
        // ---- Load B tile: 16 k x 64 n, one float4 per thread
        {
            float4 v = *reinterpret_cast<const float4*>(
                &W[(size_t)(k0 + brow) * R_DIM + colofs + bcol]);
            *reinterpret_cast<float4*>(&Bs[brow][bcol]) = v;
        }
        __syncthreads();

        // ---- FMA microkernel: 8x4 per thread
        #pragma unroll
        for (int k = 0; k < BK; ++k) {
            float4 a0 = *reinterpret_cast<const float4*>(&As[k][tr * 8]);
            float4 a1 = *reinterpret_cast<const float4*>(&As[k][tr * 8 + 4]);
            float4 b  = *reinterpret_cast<const float4*>(&Bs[k][tc * 4]);
            float av[8] = {a0.x, a0.y, a0.z, a0.w, a1.x, a1.y, a1.z, a1.w};
            float bv[4] = {b.x, b.y, b.z, b.w};
            #pragma unroll
            for (int i = 0; i < 8; ++i)
                #pragma unroll
                for (int j = 0; j < 4; ++j)
                    acc[i][j] = fmaf(av[i], bv[j], acc[i][j]);
        }
        __syncthreads();
    }

    // ---- Epilogue: exact GELU + float4 stores
    #pragma unroll
    for (int i = 0; i < 8; ++i) {
        int row = bm + tr * 8 + i;
        if (row < M_TOTAL) {
            float4 o;
            o.x = gelu_exact(acc[i][0]);
            o.y = gelu_exact(acc[i][1]);
            o.z = gelu_exact(acc[i][2]);
            o.w = gelu_exact(acc[i][3]);
            *reinterpret_cast<float4*>(&outbase[(size_t)row * R_DIM + tc * 4]) = o;
        }
    }
}

extern "C" void kernel_launch(void* const* d_in, const int* in_sizes, int n_in,
                              void* d_out, int out_size) {
    const float* X  = (const float*)d_in[0];  // [64,197,768]
    const float* Wq = (const float*)d_in[1];  // [768,192]
    const float* Wk = (const float*)d_in[2];
    const float* Wv = (const float*)d_in[3];
    float* Out = (float*)d_out;               // q||k||v, each [12608,192]

    dim3 grid(9, (M_TOTAL + BM - 1) / BM);    // 9 n-tiles, 99 m-tiles
    dim3 block(256);
    qkv_gelu_kernel<<<grid, block>>>(X, Wq, Wk, Wv, Out);
}

// round 3
// speedup vs baseline: 4.8898x; 4.8898x over previous
#include <cuda_runtime.h>
#include <cuda_fp16.h>
#include <cstdint>

#define M_TOTAL 12608   // 64*197
#define K_DIM   768
#define R_DIM   192
#define BM      128
#define BN      64
#define BK      64      // fp16 elems per chunk = 128 bytes/row
#define NCHUNK  12      // 768/64
#define A_BYTES (BM * 128)           // 16384
#define B_BYTES (BN * 128)           // 8192
#define STAGE   (A_BYTES + B_BYTES)  // 24576
#define SMEM_DYN (2 * STAGE + 1024)

#define SWZ(o) ((o) ^ (((o) >> 3) & 0x70))

// fp16 scratch (allocation-free __device__ globals)
__device__ __half g_Xh[(size_t)M_TOTAL * K_DIM];     // [M,K] row-major
__device__ __half g_Wh[(size_t)3 * R_DIM * K_DIM];   // [3][N=192][K=768] K-major

// ---------------- PTX helpers (sm_80-portable only) ----------------
__device__ __forceinline__ uint32_t smem_u32(const void* p) {
    uint32_t a;
    asm("{ .reg .u64 t; cvta.to.shared.u64 t, %1; cvt.u32.u64 %0, t; }" : "=r"(a) : "l"(p));
    return a;
}
__device__ __forceinline__ void cp16(uint32_t dst, const void* src) {
    asm volatile("cp.async.cg.shared.global [%0], [%1], 16;" :: "r"(dst), "l"(src) : "memory");
}
__device__ __forceinline__ void cp16z(uint32_t dst, const void* src, int srcbytes) {
    asm volatile("cp.async.cg.shared.global [%0], [%1], 16, %2;"
                 :: "r"(dst), "l"(src), "r"(srcbytes) : "memory");
}
#define CP_COMMIT() asm volatile("cp.async.commit_group;" ::: "memory")
#define CP_WAIT0()  asm volatile("cp.async.wait_group 0;" ::: "memory")
#define CP_WAIT1()  asm volatile("cp.async.wait_group 1;" ::: "memory")

__device__ __forceinline__ void ldsm4(uint32_t* r, uint32_t addr) {
    asm volatile("ldmatrix.sync.aligned.m8n8.x4.shared.b16 {%0,%1,%2,%3}, [%4];"
                 : "=r"(r[0]), "=r"(r[1]), "=r"(r[2]), "=r"(r[3]) : "r"(addr));
}
__device__ __forceinline__ void mma16816(float* c, const uint32_t* a, const uint32_t* b) {
    asm volatile(
        "mma.sync.aligned.m16n8k16.row.col.f32.f16.f16.f32 "
        "{%0,%1,%2,%3}, {%4,%5,%6,%7}, {%8,%9}, {%0,%1,%2,%3};"
        : "+f"(c[0]), "+f"(c[1]), "+f"(c[2]), "+f"(c[3])
        : "r"(a[0]), "r"(a[1]), "r"(a[2]), "r"(a[3]), "r"(b[0]), "r"(b[1]));
}
__device__ __forceinline__ float gelu_exact(float x) {
    return 0.5f * x * (1.0f + erff(x * 0.70710678118654752f));
}

// ---------------- convert prepasses ----------------
__global__ void cvt_x_kernel(const float4* __restrict__ X, uint2* __restrict__ out, int n4) {
    int i = blockIdx.x * blockDim.x + threadIdx.x;
    if (i < n4) {
        float4 v = X[i];
        __half2 h0 = __floats2half2_rn(v.x, v.y);
        __half2 h1 = __floats2half2_rn(v.z, v.w);
        uint2 u;
        u.x = *reinterpret_cast<uint32_t*>(&h0);
        u.y = *reinterpret_cast<uint32_t*>(&h1);
        out[i] = u;
    }
}
__global__ void cvt_w_kernel(const float* __restrict__ Wq, const float* __restrict__ Wk,
                             const float* __restrict__ Wv) {
    int idx = blockIdx.x * blockDim.x + threadIdx.x;
    const int per = R_DIM * K_DIM;
    if (idx < 3 * per) {
        int w = idx / per;
        int rem = idx - w * per;
        int n = rem / K_DIM;
        int k = rem - n * K_DIM;
        const float* W = (w == 0) ? Wq : (w == 1) ? Wk : Wv;
        g_Wh[idx] = __float2half_rn(W[k * R_DIM + n]);   // transpose -> K-major
    }
}

// ---------------- tile loaders (cp.async, swizzled 128B rows) ----------------
__device__ __forceinline__ void load_a_chunk(int c, uint32_t a_sm, int bm,
                                             const __half* __restrict__ Asrc, int tid) {
    #pragma unroll
    for (int i = 0; i < 4; ++i) {
        int idx = tid + i * 256;        // 0..1023
        int row = idx >> 3;             // 0..127
        int j   = idx & 7;              // 16B chunk
        int grow = bm + row;
        size_t roff = (grow < M_TOTAL) ? (size_t)row * K_DIM : 0;
        const void* src = Asrc + roff + c * BK + j * 8;
        cp16z(a_sm + SWZ(row * 128 + j * 16), src, (grow < M_TOTAL) ? 16 : 0);
    }
}
__device__ __forceinline__ void load_b_chunk(int c, uint32_t b_sm,
                                             const __half* __restrict__ Bsrc, int tid) {
    #pragma unroll
    for (int i = 0; i < 2; ++i) {
        int idx = tid + i * 256;        // 0..511
        int row = idx >> 3;             // 0..63 (n)
        int j   = idx & 7;
        const void* src = Bsrc + (size_t)row * K_DIM + c * BK + j * 8;
        cp16(b_sm + SWZ(row * 128 + j * 16), src);
    }
}

// ---------------- main GEMM (mma.sync HMMA) ----------------
__global__ __launch_bounds__(256, 2)
void qkv_mma_kernel(float* __restrict__ Out) {
    extern __shared__ char dynsm[];
    const int tid = threadIdx.x;
    const int wid = tid >> 5;
    const int lane = tid & 31;
    const int nb = blockIdx.x;                 // 0..8
    const int bm = blockIdx.y * BM;

    const int wsel   = nb / 3;
    const int colofs = (nb % 3) * BN;
    float* __restrict__ outbase =
        Out + (size_t)wsel * (size_t)M_TOTAL * R_DIM + colofs;

    const int warp_m = (wid & 3) * 32;         // 0,32,64,96
    const int warp_n = (wid >> 2) * 32;        // 0,32

    uint32_t base = (smem_u32(dynsm) + 1023u) & ~1023u;

    const __half* Asrc = g_Xh + (size_t)bm * K_DIM;
    const __half* Bsrc = g_Wh + ((size_t)wsel * R_DIM + colofs) * K_DIM;

    float acc[2][4][4];
    #pragma unroll
    for (int i = 0; i < 2; ++i)
        #pragma unroll
        for (int j = 0; j < 4; ++j)
            #pragma unroll
            for (int q = 0; q < 4; ++q) acc[i][j][q] = 0.0f;

    // Per-lane ldmatrix address components (byte offsets before swizzle)
    const int a_row_off = lane & 15;           // row within 16-row frag
    const int a_k_off   = (lane >> 4) * 16;    // 0 or 16 bytes (k or k+8)
    const int b_n_off   = (lane & 7) | ((lane & 16) >> 1);  // 0..15
    const int b_k_off   = (lane & 8) ? 16 : 0;

    // prologue
    load_a_chunk(0, base, bm, Asrc, tid);
    load_b_chunk(0, base + A_BYTES, Bsrc, tid);
    CP_COMMIT();

    for (int c = 0; c < NCHUNK; ++c) {
        if (c + 1 < NCHUNK) {
            uint32_t nxt = base + ((c + 1) & 1) * STAGE;
            load_a_chunk(c + 1, nxt, bm, Asrc, tid);
            load_b_chunk(c + 1, nxt + A_BYTES, Bsrc, tid);
            CP_COMMIT();
            CP_WAIT1();
        } else {
            CP_WAIT0();
        }
        __syncthreads();

        const uint32_t a_sm = base + (c & 1) * STAGE;
        const uint32_t b_sm = a_sm + A_BYTES;

        #pragma unroll
        for (int ks = 0; ks < 4; ++ks) {
            uint32_t afrag[2][4], bfrag[2][4];
            #pragma unroll
            for (int mf = 0; mf < 2; ++mf)
                ldsm4(afrag[mf],
                      a_sm + SWZ((warp_m + mf * 16 + a_row_off) * 128 + ks * 32 + a_k_off));
            #pragma unroll
            for (int nf2 = 0; nf2 < 2; ++nf2)
                ldsm4(bfrag[nf2],
                      b_sm + SWZ((warp_n + nf2 * 16 + b_n_off) * 128 + ks * 32 + b_k_off));
            #pragma unroll
            for (int mf = 0; mf < 2; ++mf)
                #pragma unroll
                for (int nf = 0; nf < 4; ++nf)
                    mma16816(acc[mf][nf], afrag[mf], &bfrag[nf >> 1][(nf & 1) * 2]);
        }
        __syncthreads();
    }

    // ---- epilogue: GELU + stores (acc frag: rows lane/4, lane/4+8; cols (lane%4)*2..+1)
    const int rbase = bm + warp_m + (lane >> 2);
    const int cbase = warp_n + (lane & 3) * 2;
    #pragma unroll
    for (int mf = 0; mf < 2; ++mf) {
        #pragma unroll
        for (int half = 0; half < 2; ++half) {
            int row = rbase + mf * 16 + half * 8;
            if (row < M_TOTAL) {
                float* op = outbase + (size_t)row * R_DIM + cbase;
                #pragma unroll
                for (int nf = 0; nf < 4; ++nf) {
                    float2 o;
                    o.x = gelu_exact(acc[mf][nf][half * 2 + 0]);
                    o.y = gelu_exact(acc[mf][nf][half * 2 + 1]);
                    *reinterpret_cast<float2*>(op + nf * 8) = o;
                }
            }
        }
    }
}

extern "C" void kernel_launch(void* const* d_in, const int* in_sizes, int n_in,
                              void* d_out, int out_size) {
    const float* X  = (const float*)d_in[0];  // [64,197,768]
    const float* Wq = (const float*)d_in[1];  // [768,192]
    const float* Wk = (const float*)d_in[2];
    const float* Wv = (const float*)d_in[3];
    float* Out = (float*)d_out;

    cudaFuncSetAttribute(qkv_mma_kernel, cudaFuncAttributeMaxDynamicSharedMemorySize, SMEM_DYN);

    __half* xh_ptr = nullptr;
    cudaGetSymbolAddress((void**)&xh_ptr, g_Xh);

    const int n4 = (M_TOTAL * K_DIM) / 4;
    cvt_x_kernel<<<(n4 + 255) / 256, 256>>>((const float4*)X, (uint2*)xh_ptr, n4);
    cvt_w_kernel<<<(3 * R_DIM * K_DIM + 255) / 256, 256>>>(Wq, Wk, Wv);

    dim3 grid(9, (M_TOTAL + BM - 1) / BM);    // 9 x 99 = 891 CTAs
    qkv_mma_kernel<<<grid, 256, SMEM_DYN>>>(Out);
}